// round 7
// baseline (speedup 1.0000x reference)
#include <cuda_runtime.h>
#include <cuda_fp16.h>
#include <cstdint>

// ============================================================================
// x (64,112,112,64) f32 NHWC; kernels (3,3,64,64) f32 HWIO (+-1); beta (64).
// out = conv3x3_SAME(BN_train(x), kernels), fp32.
//
// BN folded into GEMM: out = conv(fp16(x_raw), w*s_ci) + bias_co; padded
// border = fp16(-shift/scale). Implicit GEMM mma.sync.m16n8k16.f16,
// persistent CTAs. 8 warps = 4 m-groups x 2 n-halves; warp tile 32x32 so
// every B fragment feeds two A fragments. A staged per m-pair (cp.async
// double buffer). Race-safe ordering: wait -> pair-barrier -> issue prefetch.
// ============================================================================

#define N_  64
#define H_  112
#define W_  112
#define C_  64
#define HP  114
#define WP  114
#define M_CNT (N_*H_*W_)
#define NVEC  ((size_t)M_CNT * 16)
#define NPIX  (N_*H_*W_)
#define NTILES (NPIX/128)            // 6272
#define HW_   (H_*W_)                // 12544
#define PIXB  (C_*2)                 // 128 B per padded pixel
#define ROWB  (WP*PIXB)              // 14592 B per padded row

// B: [3 dy][192 k][72 pitch] fp16
#define BPITCH 72
#define BROWB  (BPITCH*2)            // 144
#define BCHUNKB (192*BROWB)          // 27648
#define B_BYTES (3*BCHUNKB)          // 82944

// A: per m-group [32 pixels][192 k] fp16, pitch 400B, double buffered
#define APITCH 400
#define AGBUF  (32*APITCH)           // 12800
#define SM_A0  B_BYTES
#define CONV_SMEM (B_BYTES + 4*2*AGBUF)   // 185344

// ---------------- persistent device scratch (zero-init .bss) ----------------
__device__ __align__(16) unsigned short g_xf[(size_t)N_ * HP * WP * C_];
__device__ __align__(16) unsigned short g_wb[3 * 192 * BPITCH];
__device__ float g_sum[C_];
__device__ float g_sumsq[C_];
__device__ float g_scale[C_];
__device__ float g_shift[C_];
__device__ float g_bias[C_];
__device__ unsigned short g_bord[C_];

// ============================ PTX helpers ===================================
__device__ __forceinline__ uint32_t smem_to_u32(const void* p) {
    uint32_t a;
    asm("{ .reg .u64 t; cvta.to.shared.u64 t, %1; cvt.u32.u64 %0, t; }"
        : "=r"(a) : "l"(p));
    return a;
}

#define LDSM_X4(r, addr) \
    asm volatile("ldmatrix.sync.aligned.m8n8.x4.shared.b16 {%0,%1,%2,%3}, [%4];" \
        : "=r"((r)[0]), "=r"((r)[1]), "=r"((r)[2]), "=r"((r)[3]) : "r"(addr))

#define LDSM_X4_T(r, addr) \
    asm volatile("ldmatrix.sync.aligned.m8n8.x4.trans.shared.b16 {%0,%1,%2,%3}, [%4];" \
        : "=r"((r)[0]), "=r"((r)[1]), "=r"((r)[2]), "=r"((r)[3]) : "r"(addr))

#define MMA16816(c, a, b0v, b1v) \
    asm volatile("mma.sync.aligned.m16n8k16.row.col.f32.f16.f16.f32 " \
        "{%0,%1,%2,%3}, {%4,%5,%6,%7}, {%8,%9}, {%0,%1,%2,%3};" \
        : "+f"((c)[0]), "+f"((c)[1]), "+f"((c)[2]), "+f"((c)[3]) \
        : "r"((a)[0]), "r"((a)[1]), "r"((a)[2]), "r"((a)[3]), \
          "r"(b0v), "r"(b1v))

#define CP_ASYNC16(dst_s, src_g) \
    asm volatile("cp.async.cg.shared.global [%0], [%1], 16;" \
        :: "r"(dst_s), "l"(src_g))
#define CP_COMMIT() asm volatile("cp.async.commit_group;" ::: "memory")
#define CP_WAIT0()  asm volatile("cp.async.wait_group 0;" ::: "memory")
#define BAR_SYNC(id) asm volatile("bar.sync %0, 64;" :: "r"(id) : "memory")

__device__ __forceinline__ unsigned short f2h(float f) {
    __half h = __float2half_rn(f);
    return *reinterpret_cast<unsigned short*>(&h);
}

// ---------------------------------------------------------------------------
__global__ void k_zero_stats() {
    int i = threadIdx.x;
    if (i < C_) { g_sum[i] = 0.0f; g_sumsq[i] = 0.0f; }
}

// ---------------------------------------------------------------------------
// Fused: per-channel moments + raw-x fp16 conversion into padded buffer.
__global__ void __launch_bounds__(256) k_stats_conv(const float* __restrict__ x) {
    __shared__ float ssum[C_];
    __shared__ float ssq[C_];
    int tid = threadIdx.x;
    if (tid < C_) { ssum[tid] = 0.0f; ssq[tid] = 0.0f; }
    __syncthreads();

    const float4* xv = (const float4*)x;
    uint2* of = (uint2*)g_xf;
    int g = tid & 15;
    float4 s = make_float4(0.f, 0.f, 0.f, 0.f);
    float4 q = make_float4(0.f, 0.f, 0.f, 0.f);
    size_t stride = (size_t)gridDim.x * blockDim.x;
    for (size_t i = (size_t)blockIdx.x * blockDim.x + tid; i < NVEC; i += stride) {
        float4 v = xv[i];
        s.x += v.x; s.y += v.y; s.z += v.z; s.w += v.w;
        q.x += v.x * v.x; q.y += v.y * v.y; q.z += v.z * v.z; q.w += v.w * v.w;

        size_t pix = i >> 4;
        int n   = (int)(pix / HW_);
        int rem = (int)(pix % HW_);
        int h   = rem / W_;
        int w   = rem % W_;
        unsigned short h0 = f2h(v.x), h1 = f2h(v.y), h2 = f2h(v.z), h3 = f2h(v.w);
        size_t dpix = ((size_t)n * HP + (h + 1)) * WP + (w + 1);
        of[dpix * 16 + g] = make_uint2((uint32_t)h0 | ((uint32_t)h1 << 16),
                                       (uint32_t)h2 | ((uint32_t)h3 << 16));
    }
    atomicAdd(&ssum[g * 4 + 0], s.x); atomicAdd(&ssq[g * 4 + 0], q.x);
    atomicAdd(&ssum[g * 4 + 1], s.y); atomicAdd(&ssq[g * 4 + 1], q.y);
    atomicAdd(&ssum[g * 4 + 2], s.z); atomicAdd(&ssq[g * 4 + 2], q.z);
    atomicAdd(&ssum[g * 4 + 3], s.w); atomicAdd(&ssq[g * 4 + 3], q.w);
    __syncthreads();
    if (tid < C_) {
        atomicAdd(&g_sum[tid],   ssum[tid]);
        atomicAdd(&g_sumsq[tid], ssq[tid]);
    }
}

// ---------------------------------------------------------------------------
__global__ void k_finalize(const float* __restrict__ beta) {
    int c = threadIdx.x;
    if (c < C_) {
        const float inv_m = 1.0f / (float)M_CNT;
        float m = g_sum[c] * inv_m;
        float v = g_sumsq[c] * inv_m - m * m;
        float s = rsqrtf(v + 1e-5f);
        float sh = beta[c] - m * s;
        g_scale[c] = s;
        g_shift[c] = sh;
        g_bord[c]  = f2h(-sh / s);
    }
}

// ---------------------------------------------------------------------------
__global__ void __launch_bounds__(256) k_border() {
    int idx = blockIdx.x * blockDim.x + threadIdx.x;
    if (idx >= 64 * 452 * 16) return;
    int g   = idx & 15;
    int bp  = (idx >> 4) % 452;
    int img = (idx >> 4) / 452;
    int h, w;
    if (bp < 114)      { h = 0;   w = bp; }
    else if (bp < 228) { h = 113; w = bp - 114; }
    else { int j = bp - 228; h = 1 + (j >> 1); w = (j & 1) ? 113 : 0; }
    const unsigned short* bd = g_bord;
    uint32_t v0 = (uint32_t)bd[g*4+0] | ((uint32_t)bd[g*4+1] << 16);
    uint32_t v1 = (uint32_t)bd[g*4+2] | ((uint32_t)bd[g*4+3] << 16);
    ((uint2*)g_xf)[(((size_t)img * HP + h) * WP + w) * 16 + g] = make_uint2(v0, v1);
}

// ---------------------------------------------------------------------------
__global__ void k_wprep(const float* __restrict__ kw) {
    int i = blockIdx.x * blockDim.x + threadIdx.x;
    if (i >= 36864) return;
    int cout = i & 63;
    int cin  = (i >> 6) & 63;
    int t    = i >> 12;
    int dy = t / 3, dx = t % 3;
    float v = kw[((size_t)t * 64 + cin) * 64 + cout] * g_scale[cin];
    g_wb[(size_t)dy * (192 * BPITCH) + (dx * 64 + cin) * BPITCH + cout] = f2h(v);
}

// ---------------------------------------------------------------------------
__global__ void k_bias(const float* __restrict__ kw) {
    int co = threadIdx.x;
    if (co >= C_) return;
    float acc = 0.0f;
    for (int t = 0; t < 9; t++)
        for (int ci = 0; ci < 64; ci++)
            acc += kw[((size_t)t * 64 + ci) * 64 + co] * g_shift[ci];
    g_bias[co] = acc;
}

// ---------------------------------------------------------------------------
// Conv: persistent CTAs, 256 thr = 8 warps (4 m-groups x 2 n-halves).
// Warp tile 32 pixels x 32 couts; B fragments reused across 2 A fragments.
// Per chunk: wait(all cp.async) -> pair barrier -> issue next prefetch -> MMA.
__global__ void __launch_bounds__(256, 1)
k_conv(float* __restrict__ out) {
    extern __shared__ __align__(1024) unsigned char smem[];
    uint32_t sb = smem_to_u32(smem);
    int tid = threadIdx.x;

    // stage B once
    {
        const uint4* src = (const uint4*)g_wb;
        uint4* dst = (uint4*)smem;
        for (int i = tid; i < B_BYTES / 16; i += 256) dst[i] = src[i];
    }
    __syncthreads();

    int lane = tid & 31;
    int wid  = tid >> 5;
    int mw   = wid >> 1;          // m-group 0..3
    int nw   = wid & 1;           // n-half 0..1
    int sel  = lane >> 3;
    int l7   = lane & 7;
    int barid = mw + 1;

    uint32_t agbase = sb + SM_A0 + (uint32_t)mw * (2 * AGBUF);
    uint32_t a_off  = agbase + (uint32_t)(((sel & 1) * 8 + l7) * APITCH + (sel >> 1) * 16);
    uint32_t b_base = sb + (uint32_t)(((sel & 1) * 8 + l7) * BROWB
                                      + (nw * 32 + (sel >> 1) * 8) * 2);

    // staging: 64 threads of the pair cover 32 pixels x 2 halves
    int pt      = tid & 63;
    int p_local = pt >> 1;         // 0..31
    int half    = pt & 1;
    uint32_t dst_off = (uint32_t)(p_local * APITCH + half * 192);
    const char* gx = (const char*)g_xf;

    int cq = lane & 3;
    float bia0[4], bia1[4];
    #pragma unroll
    for (int nf = 0; nf < 4; nf++) {
        bia0[nf] = g_bias[nw * 32 + nf * 8 + 2 * cq];
        bia1[nf] = g_bias[nw * 32 + nf * 8 + 2 * cq + 1];
    }

    uint32_t jj = 0;

    // prologue: prefetch first tile dy=0 into buf 0
    {
        int gp  = blockIdx.x * 128 + mw * 32 + p_local;
        int n   = gp / HW_;
        int rem = gp % HW_;
        int h   = rem / W_;
        int w   = rem % W_;
        const char* src = gx + (((size_t)n * HP + h) * WP + w) * PIXB + half * 192;
        uint32_t d = agbase + dst_off;
        #pragma unroll
        for (int i = 0; i < 12; i++) CP_ASYNC16(d + i * 16, src + i * 16);
        CP_COMMIT();
    }

    for (int tile = blockIdx.x; tile < NTILES; tile += gridDim.x) {
        int gp  = tile * 128 + mw * 32 + p_local;
        int n   = gp / HW_;
        int rem = gp % HW_;
        int h   = rem / W_;
        int w   = rem % W_;
        const char* base = gx + (((size_t)n * HP + h) * WP + w) * PIXB + half * 192;

        float c[32];
        #pragma unroll
        for (int i = 0; i < 32; i++) c[i] = 0.0f;

        #pragma unroll 1
        for (int j = 0; j < 3; j++) {
            uint32_t buf  = jj & 1;
            uint32_t nbuf = buf ^ 1;
            jj++;

            // 1) current chunk's data landed; 2) both warps done reading nbuf
            CP_WAIT0();
            BAR_SYNC(barid);

            // 3) now safe to overwrite nbuf with the next chunk
            if (j < 2) {
                const char* src = base + (size_t)(j + 1) * ROWB;
                uint32_t d = agbase + nbuf * AGBUF + dst_off;
                #pragma unroll
                for (int i = 0; i < 12; i++) CP_ASYNC16(d + i * 16, src + i * 16);
                CP_COMMIT();
            } else {
                int t2 = tile + gridDim.x;
                if (t2 < NTILES) {
                    int gp2  = t2 * 128 + mw * 32 + p_local;
                    int n2   = gp2 / HW_;
                    int rem2 = gp2 % HW_;
                    int h2   = rem2 / W_;
                    int w2   = rem2 % W_;
                    const char* src = gx + (((size_t)n2 * HP + h2) * WP + w2) * PIXB + half * 192;
                    uint32_t d = agbase + nbuf * AGBUF + dst_off;
                    #pragma unroll
                    for (int i = 0; i < 12; i++) CP_ASYNC16(d + i * 16, src + i * 16);
                    CP_COMMIT();
                }
            }

            uint32_t Abase = a_off + buf * AGBUF;
            uint32_t Bbase = b_base + j * BCHUNKB;

            #pragma unroll
            for (int s = 0; s < 12; s++) {
                uint32_t ra0[4], ra1[4], rb0[4], rb1[4];
                LDSM_X4(ra0, Abase + s * 32);
                LDSM_X4(ra1, Abase + 16 * APITCH + s * 32);
                uint32_t Bs = Bbase + s * (16 * BROWB);
                LDSM_X4_T(rb0, Bs);
                LDSM_X4_T(rb1, Bs + 32);

                MMA16816(c +  0, ra0, rb0[0], rb0[1]);
                MMA16816(c +  4, ra0, rb0[2], rb0[3]);
                MMA16816(c +  8, ra0, rb1[0], rb1[1]);
                MMA16816(c + 12, ra0, rb1[2], rb1[3]);
                MMA16816(c + 16, ra1, rb0[0], rb0[1]);
                MMA16816(c + 20, ra1, rb0[2], rb0[3]);
                MMA16816(c + 24, ra1, rb1[0], rb1[1]);
                MMA16816(c + 28, ra1, rb1[2], rb1[3]);
            }
        }

        // epilogue: add bias, store
        int r = lane >> 2;
        size_t obase = (size_t)tile * 128 * 64;
        #pragma unroll
        for (int mf = 0; mf < 2; mf++) {
            int row0 = mw * 32 + mf * 16 + r;
            float* p0 = out + obase + (size_t)row0 * 64 + nw * 32 + 2 * cq;
            float* p1 = p0 + 8 * 64;
            #pragma unroll
            for (int nf = 0; nf < 4; nf++) {
                *(float2*)(p0 + nf * 8) = make_float2(c[mf*16 + nf*4 + 0] + bia0[nf],
                                                      c[mf*16 + nf*4 + 1] + bia1[nf]);
                *(float2*)(p1 + nf * 8) = make_float2(c[mf*16 + nf*4 + 2] + bia0[nf],
                                                      c[mf*16 + nf*4 + 3] + bia1[nf]);
            }
        }
    }
}

// ---------------------------------------------------------------------------
extern "C" void kernel_launch(void* const* d_in, const int* in_sizes, int n_in,
                              void* d_out, int out_size) {
    const float* x    = (const float*)d_in[0];
    const float* kw   = (const float*)d_in[1];
    const float* beta = (const float*)d_in[2];
    float* out = (float*)d_out;
    (void)in_sizes; (void)n_in; (void)out_size;

    cudaFuncSetAttribute(k_conv, cudaFuncAttributeMaxDynamicSharedMemorySize, CONV_SMEM);

    k_zero_stats<<<1, 64>>>();
    k_stats_conv<<<2048, 256>>>(x);
    k_finalize<<<1, 64>>>(beta);
    k_border<<<(64 * 452 * 16 + 255) / 256, 256>>>();
    k_wprep<<<144, 256>>>(kw);
    k_bias<<<1, 64>>>(kw);
    k_conv<<<152, 256, CONV_SMEM>>>(out);
}